// round 15
// baseline (speedup 1.0000x reference)
#include <cuda_runtime.h>
#include <stdint.h>

// VolumeRenderer: two-pass NeRF.
// R14: TWO rays per thread, fully interleaved pipelines -> 2x per-warp ILP to
// close the latency gap toward the MUFU floor (~38us). Sampler micro-trims
// (shared frac mul, padded pre[] kills the clamp). Coarse unroll-4 + peeled
// last iteration to bound I$.

constexpr int NS = 64;
constexpr int NI = 64;
constexpr float NEARP = 2.0f;
constexpr float FARP  = 6.0f;
constexpr float EPS_W = 1e-5f;
constexpr float FAR_DIST = 1e10f;
constexpr float LOG2E = 1.44269504088896340736f;

__device__ __forceinline__ float ex2a(float x){ float y; asm("ex2.approx.f32 %0,%1;":"=f"(y):"f"(x)); return y; }
__device__ __forceinline__ float lg2a(float x){ float y; asm("lg2.approx.f32 %0,%1;":"=f"(y):"f"(x)); return y; }
__device__ __forceinline__ float tanha(float x){ float y; asm("tanh.approx.f32 %0,%1;":"=f"(y):"f"(x)); return y; }
__device__ __forceinline__ float rcpa(float x){ float y; asm("rcp.approx.f32 %0,%1;":"=f"(y):"f"(x)); return y; }

__device__ __forceinline__ float densL_cheap(float xL) {
    return lg2a(1.0f + ex2a(xL));
}
// Tail-preserving softplus*log2e — only where dist = FAR_DIST (R1 bug).
__device__ __forceinline__ float densL_exact(float xL) {
    float e = ex2a(-fabsf(xL));
    float lsmall = (e * LOG2E) * fmaf(e, fmaf(e, 0.33333334f, -0.5f), 1.0f);
    float lbig   = lg2a(1.0f + e);
    float l = (e < 0.03f) ? lsmall : lbig;
    return fmaxf(xL, 0.0f) + l;
}

__global__ __launch_bounds__(128)
void volume_render_kernel(const float* __restrict__ ro_g,
                          const float* __restrict__ rd_g,
                          const float* __restrict__ Wd_g,
                          const float* __restrict__ Wc_g,
                          float* __restrict__ out,
                          int N, long long out_size)
{
    const int pair = blockIdx.x * blockDim.x + threadIdx.x;
    const int rayA = pair * 2;
    if (rayA >= N) return;
    const bool hasB = (rayA + 1) < N;
    const int rayB = hasB ? (rayA + 1) : rayA;

    const long long NL = (long long)N;
    const float STEP = (FARP - NEARP) / 63.0f;

    const float wd0 = __ldg(Wd_g+0), wd1 = __ldg(Wd_g+1), wd2 = __ldg(Wd_g+2);
    const float w00=__ldg(Wc_g+0), w01=__ldg(Wc_g+1), w02=__ldg(Wc_g+2);
    const float w10=__ldg(Wc_g+3), w11=__ldg(Wc_g+4), w12=__ldg(Wc_g+5);
    const float w20=__ldg(Wc_g+6), w21=__ldg(Wc_g+7), w22=__ldg(Wc_g+8);

    int   rid[2] = {rayA, rayB};
    float A0L[2], B0L[2], AcH[2][3], BcH[2][3];

    #pragma unroll
    for (int r = 0; r < 2; r++) {
        const int rr = rid[r];
        float ro0 = ro_g[rr*3+0], ro1 = ro_g[rr*3+1], ro2 = ro_g[rr*3+2];
        float rd0 = rd_g[rr*3+0], rd1 = rd_g[rr*3+1], rd2 = rd_g[rr*3+2];
        A0L[r] = (ro0*wd0 + ro1*wd1 + ro2*wd2) * LOG2E;
        B0L[r] = (rd0*wd0 + rd1*wd1 + rd2*wd2) * LOG2E;
        AcH[r][0] = 0.5f*(ro0*w00 + ro1*w10 + ro2*w20);
        AcH[r][1] = 0.5f*(ro0*w01 + ro1*w11 + ro2*w21);
        AcH[r][2] = 0.5f*(ro0*w02 + ro1*w12 + ro2*w22);
        BcH[r][0] = 0.5f*(rd0*w00 + rd1*w10 + rd2*w20);
        BcH[r][1] = 0.5f*(rd0*w01 + rd1*w11 + rd2*w21);
        BcH[r][2] = 0.5f*(rd0*w02 + rd1*w12 + rd2*w22);
    }

    // -------- coarse pass, both rays interleaved --------
    float pre[2][NS+3];                    // padded: drop clamp in fine loop
    float sumL[2] = {0.f, 0.f};
    float Tp[2]   = {1.f, 1.f};
    float prew[2] = {0.f, 0.f};
    float cr[2][3] = {{0,0,0},{0,0,0}};
    float cdep[2] = {0.f, 0.f};
    float g[2], gr[2];
    #pragma unroll
    for (int r = 0; r < 2; r++) {
        pre[r][0] = 0.0f;
        g[r]  = ex2a(fmaf(B0L[r], NEARP, A0L[r]));
        gr[r] = ex2a(B0L[r] * STEP);
    }

    #pragma unroll 4
    for (int i = 0; i < NS-1; i++) {
        float t = fmaf((float)i, STEP, NEARP);
        #pragma unroll
        for (int r = 0; r < 2; r++) {
            float inc = lg2a(1.0f + g[r]) * STEP;
            g[r] *= gr[r];
            sumL[r] += inc;
            float Tn = ex2a(-sumL[r]);
            float wi = Tp[r] - Tn;
            prew[r] += wi + EPS_W;
            pre[r][i+1] = prew[r];
            float wh = 0.5f * wi;
            cr[r][0] += fmaf(wh, tanha(fmaf(BcH[r][0], t, AcH[r][0])), wh);
            cr[r][1] += fmaf(wh, tanha(fmaf(BcH[r][1], t, AcH[r][1])), wh);
            cr[r][2] += fmaf(wh, tanha(fmaf(BcH[r][2], t, AcH[r][2])), wh);
            cdep[r] = fmaf(wi, t, cdep[r]);
            Tp[r] = Tn;
        }
    }
    // peeled i = 63: dist = FAR_DIST, exact density tail
    #pragma unroll
    for (int r = 0; r < 2; r++) {
        float inc = densL_exact(fmaf(B0L[r], FARP, A0L[r])) * FAR_DIST;
        sumL[r] += inc;
        float Tn = ex2a(-sumL[r]);
        float wi = Tp[r] - Tn;
        prew[r] += wi + EPS_W;
        pre[r][NS]   = prew[r];
        pre[r][NS+1] = prew[r];            // padding (fine loop reads b+2<=65)
        pre[r][NS+2] = prew[r];
        float wh = 0.5f * wi;
        cr[r][0] += fmaf(wh, tanha(fmaf(BcH[r][0], FARP, AcH[r][0])), wh);
        cr[r][1] += fmaf(wh, tanha(fmaf(BcH[r][1], FARP, AcH[r][1])), wh);
        cr[r][2] += fmaf(wh, tanha(fmaf(BcH[r][2], FARP, AcH[r][2])), wh);
        cdep[r] = fmaf(wi, FARP, cdep[r]);
    }

    float wsum[2], acc[2];
    #pragma unroll
    for (int r = 0; r < 2; r++) {
        wsum[r] = prew[r];
        acc[r]  = wsum[r] - (float)NS * EPS_W;
    }

    // coarse outputs
    #pragma unroll
    for (int r = 0; r < 2; r++) {
        if (r == 1 && !hasB) break;
        const long long rr = rid[r];
        if (3*NL <= out_size) {
            out[rr*3+0] = cr[r][0] + (1.0f - acc[r]);
            out[rr*3+1] = cr[r][1] + (1.0f - acc[r]);
            out[rr*3+2] = cr[r][2] + (1.0f - acc[r]);
        }
        if (4*NL <= out_size) out[3*NL + rr] = cdep[r];
        if (5*NL <= out_size) out[4*NL + rr] = acc[r];
    }

    // -------- fine pass, both rays interleaved --------
    float inv_wsum[2], epsw_s[2], dws[2];
    int   b[2] = {0, 0};
    float tb[2]    = {NEARP, NEARP};
    float preb[2]  = {0.f, 0.f};
    float preb1[2], pnext[2], ukw[2] = {0.f, 0.f};
    float pend[2]  = {NEARP, NEARP};
    float pdL[2], pc[2][3];
    float fsum[2] = {0.f, 0.f};
    float fTp[2]  = {1.f, 1.f};
    float fr[2][3] = {{0,0,0},{0,0,0}};
    float fdep[2] = {0.f, 0.f};
    float facc[2] = {0.f, 0.f};

    #pragma unroll
    for (int r = 0; r < 2; r++) {
        inv_wsum[r] = rcpa(wsum[r]);
        epsw_s[r]   = EPS_W * wsum[r];
        dws[r]      = wsum[r] * (1.0f/63.0f);
        preb1[r]    = pre[r][1];
        pnext[r]    = pre[r][2];
        pdL[r]      = densL_cheap(fmaf(B0L[r], NEARP, A0L[r]));
        pc[r][0]    = tanha(fmaf(BcH[r][0], NEARP, AcH[r][0]));
        pc[r][1]    = tanha(fmaf(BcH[r][1], NEARP, AcH[r][1]));
        pc[r][2]    = tanha(fmaf(BcH[r][2], NEARP, AcH[r][2]));
    }

    #pragma unroll 1
    for (int it = 1; it < NS + NI; it++) {
        #pragma unroll
        for (int r = 0; r < 2; r++) {
            // ---- branchless selection ----
            bool  last = (b[r] == NS-1);
            bool  imp  = (ukw[r] < preb1[r]) || last;
            float diff = preb1[r] - preb[r];
            float num  = ukw[r] - preb[r];
            float rr   = (diff < epsw_s[r]) ? inv_wsum[r] : rcpa(diff);
            float frac = num * rr;
            float dt   = last ? 0.0f : STEP;
            float s_adv = tb[r] + STEP;
            float s     = imp ? fmaf(frac, dt, tb[r]) : s_adv;

            ukw[r]  = imp ? (ukw[r] + dws[r]) : ukw[r];
            b[r]    = imp ? b[r]    : (b[r] + 1);
            tb[r]   = imp ? tb[r]   : s_adv;
            preb[r] = imp ? preb[r] : preb1[r];
            preb1[r]= imp ? preb1[r]: pnext[r];
            pnext[r]= pre[r][b[r] + 2];      // padded, no clamp

            // ---- render pending sample ----
            fsum[r] = fmaf(pdL[r], s - pend[r], fsum[r]);
            float Tn = ex2a(-fsum[r]);
            float wi = fTp[r] - Tn;
            float wh = 0.5f * wi;
            fr[r][0] += fmaf(wh, pc[r][0], wh);
            fr[r][1] += fmaf(wh, pc[r][1], wh);
            fr[r][2] += fmaf(wh, pc[r][2], wh);
            fdep[r] = fmaf(wi, pend[r], fdep[r]);
            facc[r] += wi;
            fTp[r] = Tn;

            // ---- pipeline MUFUs for new sample ----
            pend[r] = s;
            pdL[r]  = densL_cheap(fmaf(B0L[r], s, A0L[r]));
            pc[r][0] = tanha(fmaf(BcH[r][0], s, AcH[r][0]));
            pc[r][1] = tanha(fmaf(BcH[r][1], s, AcH[r][1]));
            pc[r][2] = tanha(fmaf(BcH[r][2], s, AcH[r][2]));
        }
    }
    // tail sample (pend = t63), dist = FAR_DIST, exact density
    #pragma unroll
    for (int r = 0; r < 2; r++) {
        float dL = densL_exact(fmaf(B0L[r], pend[r], A0L[r]));
        fsum[r] = fmaf(dL, FAR_DIST, fsum[r]);
        float Tn = ex2a(-fsum[r]);
        float wi = fTp[r] - Tn;
        float wh = 0.5f * wi;
        fr[r][0] += fmaf(wh, pc[r][0], wh);
        fr[r][1] += fmaf(wh, pc[r][1], wh);
        fr[r][2] += fmaf(wh, pc[r][2], wh);
        fdep[r] = fmaf(wi, pend[r], fdep[r]);
        facc[r] += wi;
    }

    // fine outputs
    #pragma unroll
    for (int r = 0; r < 2; r++) {
        if (r == 1 && !hasB) break;
        const long long rr = rid[r];
        if (8*NL <= out_size) {
            out[5*NL + rr*3 + 0] = fr[r][0] + (1.0f - facc[r]);
            out[5*NL + rr*3 + 1] = fr[r][1] + (1.0f - facc[r]);
            out[5*NL + rr*3 + 2] = fr[r][2] + (1.0f - facc[r]);
        }
        if (9*NL  <= out_size) out[8*NL + rr] = fdep[r];
        if (10*NL <= out_size) out[9*NL + rr] = facc[r];
    }
}

extern "C" void kernel_launch(void* const* d_in, const int* in_sizes, int n_in,
                              void* d_out, int out_size)
{
    const float* Wd = nullptr;
    const float* Wc = nullptr;
    for (int i = 0; i < n_in; i++) {
        if (in_sizes[i] == 3) Wd = (const float*)d_in[i];
        else if (in_sizes[i] == 9) Wc = (const float*)d_in[i];
    }
    int N = (out_size % 10 == 0) ? (out_size / 10) : (in_sizes[0] / 3);

    const float* ro = nullptr;
    const float* rd = nullptr;
    for (int i = 0; i < n_in; i++) {
        if (in_sizes[i] == 3 * N && in_sizes[i] > 9) {
            if (!ro) ro = (const float*)d_in[i];
            else if (!rd) { rd = (const float*)d_in[i]; break; }
        }
    }
    if (!ro || !rd) { ro = (const float*)d_in[0]; rd = (const float*)d_in[1]; }
    if (!Wd) Wd = (const float*)d_in[3];
    if (!Wc) Wc = (const float*)d_in[4];

    float* out = (float*)d_out;
    const int threads = 128;
    const int npairs  = (N + 1) / 2;
    const int blocks  = (npairs + threads - 1) / threads;
    volume_render_kernel<<<blocks, threads>>>(ro, rd, Wd, Wc, out,
                                              N, (long long)out_size);
}